// round 3
// baseline (speedup 1.0000x reference)
#include <cuda_runtime.h>
#include <cuda_bf16.h>
#include <math.h>

// Problem constants (fixed shapes)
#define BB 8
#define CC 256
#define HH 56
#define WW 56
#define HWHW 3136            // 56*56
#define NPIX 25088           // B*H*W
#define NF 6422528           // B*C*H*W
#define RR 2
#define HID 64

// ---------------------------------------------------------------------------
// packed f32x2 helpers (Blackwell: FFMA2 doubles fp32 FMA throughput vs FFMA)
__device__ __forceinline__ unsigned long long fma_f32x2(
    unsigned long long a, unsigned long long b, unsigned long long c)
{
    unsigned long long d;
    asm("fma.rn.f32x2 %0, %1, %2, %3;" : "=l"(d) : "l"(a), "l"(b), "l"(c));
    return d;
}
__device__ __forceinline__ unsigned long long pack2(float lo, float hi)
{
    unsigned long long d;
    asm("mov.b64 %0, {%1, %2};" : "=l"(d) : "f"(lo), "f"(hi));
    return d;
}
__device__ __forceinline__ void unpack2(unsigned long long v, float& lo, float& hi)
{
    asm("mov.b64 {%0, %1}, %2;" : "=f"(lo), "=f"(hi) : "l"(v));
}

// ---------------------------------------------------------------------------
// Scratch: single device global (no allocations allowed). ~173 MB.
__device__ __align__(16) float g_scratch[43200000];

// ---------------------------------------------------------------------------
// 1) TargetRegionDecoupler: logits = dec_w . F, softmax over R=2, F_i = F*(1+m_i)
__global__ void __launch_bounds__(256) k_decouple(
    const float* __restrict__ F, const float* __restrict__ dw,
    const float* __restrict__ db, float* __restrict__ F0, float* __restrict__ F1)
{
    int p = blockIdx.x * 256 + threadIdx.x;
    if (p >= NPIX) return;
    int b = p / HWHW, s = p - b * HWHW;
    const float* base = F + (size_t)b * CC * HWHW + s;
    float l0 = db[0], l1 = db[1];
#pragma unroll 4
    for (int c = 0; c < CC; ++c) {
        float v = base[c * HWHW];
        l0 += v * dw[c];
        l1 += v * dw[CC + c];
    }
    float m0 = 1.0f / (1.0f + expf(l1 - l0));   // softmax (R=2) -> sigmoid
    float m1 = 1.0f - m0;
    float* o0 = F0 + (size_t)b * CC * HWHW + s;
    float* o1 = F1 + (size_t)b * CC * HWHW + s;
#pragma unroll 4
    for (int c = 0; c < CC; ++c) {
        float v = base[c * HWHW];
        o0[c * HWHW] = v * (1.0f + m0);
        o1[c * HWHW] = v * (1.0f + m1);
    }
}

// ---------------------------------------------------------------------------
// fused weight transposes:  w[OC][K] -> wT[K][OCpad]  for all 5 weight blobs
__global__ void k_wtrans_all(
    const float* __restrict__ o1w, const float* __restrict__ o2w,
    const float* __restrict__ pww,
    float* __restrict__ wT1, float* __restrict__ wT2, float* __restrict__ wTp)
{
    int idx = blockIdx.x * 256 + threadIdx.x;
    // segment sizes (in wT elements): 2*2304*64, 2*576*64, 512*256
    if (idx < 2 * 2304 * 64) {
        int r = idx / (2304 * 64); int e = idx - r * 2304 * 64;
        int k = e / 64, oc = e - k * 64;
        wT1[idx] = (oc < 64) ? o1w[(size_t)r * 64 * 2304 + oc * 2304 + k] : 0.0f;
        return;
    }
    idx -= 2 * 2304 * 64;
    if (idx < 2 * 576 * 64) {
        int r = idx / (576 * 64); int e = idx - r * 576 * 64;
        int k = e / 64, oc = e - k * 64;
        wT2[r * 576 * 64 + e] = (oc < 18) ? o2w[(size_t)r * 18 * 576 + oc * 576 + k] : 0.0f;
        return;
    }
    idx -= 2 * 576 * 64;
    if (idx < 512 * 256) {
        int k = idx / 256, oc = idx - k * 256;
        wTp[idx] = pww[oc * 512 + k];
    }
}

// ---------------------------------------------------------------------------
// B-fragment loader (im2col on the fly) for 3x3 conv, pad=1
template<int IC>
__device__ __forceinline__ void conv_loadB(
    const float* __restrict__ inb, int my, int mx, int k0, float b[8])
{
#pragma unroll
    for (int j = 0; j < 8; ++j) {
        int k = k0 + j;
        int ic = k / 9, tap = k - ic * 9;
        int ky = tap / 3, kx = tap - ky * 3;
        int yy = my + ky - 1, xx = mx + kx - 1;
        float v = 0.0f;
        if ((unsigned)yy < (unsigned)HH && (unsigned)xx < (unsigned)WW)
            v = __ldg(&inb[ic * HWHW + yy * WW + xx]);
        b[j] = v;
    }
}

// ---------------------------------------------------------------------------
// 2) 3x3 conv as implicit GEMM, pad=1.  64oc x 128px tile, 128 threads,
//    8x8 microtile with packed f32x2 FMA (oc pairs). Double-buffered smem.
//    blockIdx.y = region (0/1).
template<int IC, int OC, bool RELU>
__global__ void __launch_bounds__(128) k_conv3(
    const float* __restrict__ in0, const float* __restrict__ in1,
    const float* __restrict__ wTb, const float* __restrict__ biasb,
    float* __restrict__ out0, float* __restrict__ out1)
{
    const int K = IC * 9;
    const int NT = K / 8;
    int r = blockIdx.y;
    const float* in   = r ? in1 : in0;
    const float* wT   = wTb + (size_t)r * K * 64;
    const float* bias = biasb + r * OC;
    float* out = r ? out1 : out0;

    __shared__ __align__(16) float As[2][8][64];
    __shared__ __align__(16) unsigned long long Bs[2][8][128];

    int tid = threadIdx.x;
    int tr = tid >> 4, tcn = tid & 15;
    int px0 = blockIdx.x * 128;
    int mypx = px0 + tid;
    int mb = mypx / HWHW; int ms = mypx - mb * HWHW;
    int my = ms / WW, mx = ms - my * WW;
    const float* inb = in + (size_t)mb * IC * HWHW;

    unsigned long long acc2[4][8];
#pragma unroll
    for (int i = 0; i < 4; ++i)
#pragma unroll
        for (int j = 0; j < 8; ++j) acc2[i][j] = 0ULL;

    float bReg[8], aReg[4];
    // prologue: tile 0
    conv_loadB<IC>(inb, my, mx, 0, bReg);
#pragma unroll
    for (int j = 0; j < 4; ++j)
        aReg[j] = wT[((tid >> 6) + j * 2) * 64 + (tid & 63)];
#pragma unroll
    for (int j = 0; j < 8; ++j) Bs[0][j][tid] = pack2(bReg[j], bReg[j]);
#pragma unroll
    for (int j = 0; j < 4; ++j) As[0][(tid >> 6) + j * 2][tid & 63] = aReg[j];
    __syncthreads();

    int buf = 0;
    for (int t = 0; t < NT; ++t) {
        if (t + 1 < NT) {
            conv_loadB<IC>(inb, my, mx, (t + 1) * 8, bReg);
#pragma unroll
            for (int j = 0; j < 4; ++j)
                aReg[j] = wT[((t + 1) * 8 + (tid >> 6) + j * 2) * 64 + (tid & 63)];
        }
#pragma unroll
        for (int kk = 0; kk < 8; ++kk) {
            ulonglong2 ua0 = *(const ulonglong2*)&As[buf][kk][tr * 8];
            ulonglong2 ua1 = *(const ulonglong2*)&As[buf][kk][tr * 8 + 4];
            ulonglong2 ub0 = *(const ulonglong2*)&Bs[buf][kk][tcn * 8];
            ulonglong2 ub1 = *(const ulonglong2*)&Bs[buf][kk][tcn * 8 + 2];
            ulonglong2 ub2 = *(const ulonglong2*)&Bs[buf][kk][tcn * 8 + 4];
            ulonglong2 ub3 = *(const ulonglong2*)&Bs[buf][kk][tcn * 8 + 6];
            unsigned long long A2[4] = { ua0.x, ua0.y, ua1.x, ua1.y };
            unsigned long long Bv[8] = { ub0.x, ub0.y, ub1.x, ub1.y,
                                         ub2.x, ub2.y, ub3.x, ub3.y };
#pragma unroll
            for (int i2 = 0; i2 < 4; ++i2)
#pragma unroll
                for (int j = 0; j < 8; ++j)
                    acc2[i2][j] = fma_f32x2(A2[i2], Bv[j], acc2[i2][j]);
        }
        if (t + 1 < NT) {
            int nb = buf ^ 1;
#pragma unroll
            for (int j = 0; j < 8; ++j) Bs[nb][j][tid] = pack2(bReg[j], bReg[j]);
#pragma unroll
            for (int j = 0; j < 4; ++j) As[nb][(tid >> 6) + j * 2][tid & 63] = aReg[j];
            __syncthreads();
            buf = nb;
        }
    }

#pragma unroll
    for (int i2 = 0; i2 < 4; ++i2) {
        int oc0 = tr * 8 + i2 * 2, oc1 = oc0 + 1;
        float bv0 = (oc0 < OC) ? bias[oc0] : 0.0f;
        float bv1 = (oc1 < OC) ? bias[oc1] : 0.0f;
#pragma unroll
        for (int j = 0; j < 8; ++j) {
            float lo, hi; unpack2(acc2[i2][j], lo, hi);
            int px = px0 + tcn * 8 + j;
            int b2 = px / HWHW, s2 = px - b2 * HWHW;
            if (oc0 < OC) {
                float v = lo + bv0; if (RELU) v = fmaxf(v, 0.0f);
                out[((size_t)b2 * OC + oc0) * HWHW + s2] = v;
            }
            if (oc1 < OC) {
                float v = hi + bv1; if (RELU) v = fmaxf(v, 0.0f);
                out[((size_t)b2 * OC + oc1) * HWHW + s2] = v;
            }
        }
    }
}

// ---------------------------------------------------------------------------
// 3) NCHW -> NHWC transpose (per region via blockIdx.z = r*8 + b)
__global__ void k_tr(const float* __restrict__ s0, const float* __restrict__ s1,
                     float* __restrict__ d0, float* __restrict__ d1)
{
    __shared__ float tile[32][33];
    int z = blockIdx.z; int r = z >> 3, b = z & 7;
    const float* src = (r ? s1 : s0) + (size_t)b * CC * HWHW;
    float* dst = (r ? d1 : d0) + (size_t)b * HWHW * CC;
    int c0 = blockIdx.y * 32, sp0 = blockIdx.x * 32;
    int tx = threadIdx.x, ty = threadIdx.y;
#pragma unroll
    for (int i = ty; i < 32; i += 8)
        tile[i][tx] = src[(c0 + i) * HWHW + sp0 + tx];
    __syncthreads();
#pragma unroll
    for (int i = ty; i < 32; i += 8)
        dst[(size_t)(sp0 + i) * CC + c0 + tx] = tile[tx][i];
}

// ---------------------------------------------------------------------------
// 4) AKG part 1: 8x8 exact adaptive mean pool (56->7), depthwise 3x3 pad1 +
//    relu, global mean -> dvec[b*C+c].  One block per (r,b,c).
__global__ void __launch_bounds__(64) k_akgpool(
    const float* __restrict__ F0, const float* __restrict__ F1,
    const float* __restrict__ dwwb, float* __restrict__ dvec)
{
    int gb = blockIdx.x; int r = gb >> 11; int bc = gb & 2047;
    int c = bc & 255;
    const float* P = (r ? F1 : F0) + (size_t)bc * HWHW;
    const float* dww = dwwb + r * CC * 9 + c * 9;
    __shared__ float pool[49];
    __shared__ float cnv[49];
    int t = threadIdx.x;
    if (t < 49) {
        int bi = t / 7, bj = t - bi * 7;
        const float* q = P + bi * 8 * WW + bj * 8;
        float sm = 0.0f;
#pragma unroll
        for (int u = 0; u < 8; ++u)
#pragma unroll
            for (int v = 0; v < 8; ++v) sm += q[u * WW + v];
        pool[t] = sm * 0.015625f;
    }
    __syncthreads();
    if (t < 49) {
        int pi = t / 7, pj = t - pi * 7;
        float sm = 0.0f;
#pragma unroll
        for (int u = 0; u < 3; ++u)
#pragma unroll
            for (int v = 0; v < 3; ++v) {
                int yy = pi + u - 1, xx = pj + v - 1;
                if ((unsigned)yy < 7u && (unsigned)xx < 7u)
                    sm += dww[u * 3 + v] * pool[yy * 7 + xx];
            }
        cnv[t] = fmaxf(sm, 0.0f);
    }
    __syncthreads();
    if (t == 0) {
        float sm = 0.0f;
        for (int i = 0; i < 49; ++i) sm += cnv[i];
        dvec[r * 2048 + bc] = sm * (1.0f / 49.0f);
    }
}

// 5) AKG part 2: 1x1 head (2304x256) + tanh -> K[b][c*9+t]
__global__ void __launch_bounds__(256) k_akghead(
    const float* __restrict__ dvec, const float* __restrict__ hwb,
    const float* __restrict__ hbb, float* __restrict__ Kout)
{
    int b = blockIdx.x, r = blockIdx.y;
    const float* hw = hwb + (size_t)r * 2304 * 256;
    const float* hb = hbb + r * 2304;
    __shared__ float dv[256];
    dv[threadIdx.x] = dvec[r * 2048 + b * 256 + threadIdx.x];
    __syncthreads();
    for (int oc = threadIdx.x; oc < 2304; oc += 256) {
        const float* w = hw + (size_t)oc * 256;
        float sm = hb[oc];
#pragma unroll 8
        for (int c2 = 0; c2 < 256; ++c2) sm += w[c2] * dv[c2];
        Kout[(r * 8 + b) * 2304 + oc] = tanhf(sm);
    }
}

// ---------------------------------------------------------------------------
// 6) dynamic depthwise deformable conv (NHWC gather).
__global__ void __launch_bounds__(256) k_deform(
    const float* __restrict__ F0n, const float* __restrict__ F1n,
    const float* __restrict__ p0, const float* __restrict__ p1,
    const float* __restrict__ Kall, float* __restrict__ D0, float* __restrict__ D1)
{
    int y = blockIdx.x, b = blockIdx.y, r = blockIdx.z;
    const float* Fn = (r ? F1n : F0n) + (size_t)b * HWHW * CC;
    const float* off = (r ? p1 : p0) + (size_t)b * 18 * HWHW;
    const float* Kw = Kall + (r * 8 + b) * 2304;
    float* Dn = (r ? D1 : D0) + (size_t)b * HWHW * CC;

    __shared__ int   sIdx[9][56][4];
    __shared__ float sW[9][56][4];
    __shared__ float sK[9][256];
    int tid = threadIdx.x;
    for (int i = tid; i < 2304; i += 256) {
        int c = i / 9, t = i - c * 9;
        sK[t][c] = Kw[i];
    }
    for (int i = tid; i < 504; i += 256) {
        int t = i / 56, x = i - t * 56;
        int ky = t / 3, kx = t - ky * 3;
        float dy = off[(2 * t) * HWHW + y * WW + x];
        float dx = off[(2 * t + 1) * HWHW + y * WW + x];
        float py = (float)(y + ky - 1) + dy;
        float px = (float)(x + kx - 1) + dx;
        float fy = floorf(py), fx = floorf(px);
        float wy1 = py - fy, wx1 = px - fx;
        float wy0 = 1.0f - wy1, wx0 = 1.0f - wx1;
        int y0 = (int)fy, x0 = (int)fx;
        int y1 = y0 + 1, x1 = x0 + 1;
        bool vy0 = (y0 >= 0) && (y0 < HH);
        bool vy1 = (y1 >= 0) && (y1 < HH);
        bool vx0 = (x0 >= 0) && (x0 < WW);
        bool vx1 = (x1 >= 0) && (x1 < WW);
        int cy0 = min(max(y0, 0), HH - 1), cy1 = min(max(y1, 0), HH - 1);
        int cx0 = min(max(x0, 0), WW - 1), cx1 = min(max(x1, 0), WW - 1);
        sIdx[t][x][0] = (cy0 * WW + cx0) * CC; sW[t][x][0] = (vy0 && vx0) ? wy0 * wx0 : 0.0f;
        sIdx[t][x][1] = (cy0 * WW + cx1) * CC; sW[t][x][1] = (vy0 && vx1) ? wy0 * wx1 : 0.0f;
        sIdx[t][x][2] = (cy1 * WW + cx0) * CC; sW[t][x][2] = (vy1 && vx0) ? wy1 * wx0 : 0.0f;
        sIdx[t][x][3] = (cy1 * WW + cx1) * CC; sW[t][x][3] = (vy1 && vx1) ? wy1 * wx1 : 0.0f;
    }
    __syncthreads();
    int lane = tid & 31, wrp = tid >> 5;   // 8 warps; warp owns x stripe
    for (int x = wrp; x < 56; x += 8) {
        float acc[8];
#pragma unroll
        for (int q = 0; q < 8; ++q) acc[q] = 0.0f;
#pragma unroll
        for (int t = 0; t < 9; ++t) {
            int i0 = sIdx[t][x][0], i1 = sIdx[t][x][1];
            int i2 = sIdx[t][x][2], i3 = sIdx[t][x][3];
            float w0 = sW[t][x][0], w1 = sW[t][x][1];
            float w2 = sW[t][x][2], w3 = sW[t][x][3];
#pragma unroll
            for (int q = 0; q < 8; ++q) {
                int c = q * 32 + lane;
                float v = w0 * Fn[i0 + c] + w1 * Fn[i1 + c]
                        + w2 * Fn[i2 + c] + w3 * Fn[i3 + c];
                acc[q] += sK[t][c] * v;
            }
        }
        float* o = Dn + ((size_t)y * WW + x) * CC;
#pragma unroll
        for (int q = 0; q < 8; ++q) o[q * 32 + lane] = acc[q];
    }
}

// ---------------------------------------------------------------------------
// 7) pw2 1x1 conv over concat(D0,D1) (K=512), NHWC input, NCHW output.
//    packed f32x2 microtile + double buffering.
__global__ void __launch_bounds__(128) k_pw2(
    const float* __restrict__ D0, const float* __restrict__ D1,
    const float* __restrict__ wT, const float* __restrict__ bias,
    float* __restrict__ out)
{
    __shared__ __align__(16) float As[2][8][64];
    __shared__ __align__(16) unsigned long long Bs[2][8][128];
    int tid = threadIdx.x;
    int tr = tid >> 4, tcn = tid & 15;
    int px0 = blockIdx.x * 128;
    int ocb = blockIdx.y * 64;
    int mypx = px0 + tid;

    unsigned long long acc2[4][8];
#pragma unroll
    for (int i = 0; i < 4; ++i)
#pragma unroll
        for (int j = 0; j < 8; ++j) acc2[i][j] = 0ULL;

    float bReg[8], aReg[4];
    {
        const float* src = D0 + (size_t)mypx * 256;
        float4 v0 = *(const float4*)src;
        float4 v1 = *(const float4*)(src + 4);
        bReg[0]=v0.x; bReg[1]=v0.y; bReg[2]=v0.z; bReg[3]=v0.w;
        bReg[4]=v1.x; bReg[5]=v1.y; bReg[6]=v1.z; bReg[7]=v1.w;
#pragma unroll
        for (int j = 0; j < 4; ++j)
            aReg[j] = wT[((tid >> 6) + j * 2) * 256 + ocb + (tid & 63)];
    }
#pragma unroll
    for (int j = 0; j < 8; ++j) Bs[0][j][tid] = pack2(bReg[j], bReg[j]);
#pragma unroll
    for (int j = 0; j < 4; ++j) As[0][(tid >> 6) + j * 2][tid & 63] = aReg[j];
    __syncthreads();

    int buf = 0;
    for (int t = 0; t < 64; ++t) {
        if (t + 1 < 64) {
            int k0 = (t + 1) * 8;
            const float* src = (k0 < 256) ? (D0 + (size_t)mypx * 256 + k0)
                                          : (D1 + (size_t)mypx * 256 + (k0 - 256));
            float4 v0 = *(const float4*)src;
            float4 v1 = *(const float4*)(src + 4);
            bReg[0]=v0.x; bReg[1]=v0.y; bReg[2]=v0.z; bReg[3]=v0.w;
            bReg[4]=v1.x; bReg[5]=v1.y; bReg[6]=v1.z; bReg[7]=v1.w;
#pragma unroll
            for (int j = 0; j < 4; ++j)
                aReg[j] = wT[(k0 + (tid >> 6) + j * 2) * 256 + ocb + (tid & 63)];
        }
#pragma unroll
        for (int kk = 0; kk < 8; ++kk) {
            ulonglong2 ua0 = *(const ulonglong2*)&As[buf][kk][tr * 8];
            ulonglong2 ua1 = *(const ulonglong2*)&As[buf][kk][tr * 8 + 4];
            ulonglong2 ub0 = *(const ulonglong2*)&Bs[buf][kk][tcn * 8];
            ulonglong2 ub1 = *(const ulonglong2*)&Bs[buf][kk][tcn * 8 + 2];
            ulonglong2 ub2 = *(const ulonglong2*)&Bs[buf][kk][tcn * 8 + 4];
            ulonglong2 ub3 = *(const ulonglong2*)&Bs[buf][kk][tcn * 8 + 6];
            unsigned long long A2[4] = { ua0.x, ua0.y, ua1.x, ua1.y };
            unsigned long long Bv[8] = { ub0.x, ub0.y, ub1.x, ub1.y,
                                         ub2.x, ub2.y, ub3.x, ub3.y };
#pragma unroll
            for (int i2 = 0; i2 < 4; ++i2)
#pragma unroll
                for (int j = 0; j < 8; ++j)
                    acc2[i2][j] = fma_f32x2(A2[i2], Bv[j], acc2[i2][j]);
        }
        if (t + 1 < 64) {
            int nb = buf ^ 1;
#pragma unroll
            for (int j = 0; j < 8; ++j) Bs[nb][j][tid] = pack2(bReg[j], bReg[j]);
#pragma unroll
            for (int j = 0; j < 4; ++j) As[nb][(tid >> 6) + j * 2][tid & 63] = aReg[j];
            __syncthreads();
            buf = nb;
        }
    }

#pragma unroll
    for (int i2 = 0; i2 < 4; ++i2) {
        int oc0 = ocb + tr * 8 + i2 * 2, oc1 = oc0 + 1;
        float bv0 = bias[oc0], bv1 = bias[oc1];
#pragma unroll
        for (int j = 0; j < 8; ++j) {
            float lo, hi; unpack2(acc2[i2][j], lo, hi);
            int px = px0 + tcn * 8 + j;
            int b2 = px / HWHW, s2 = px - b2 * HWHW;
            out[((size_t)b2 * CC + oc0) * HWHW + s2] = lo + bv0;
            out[((size_t)b2 * CC + oc1) * HWHW + s2] = hi + bv1;
        }
    }
}

// ---------------------------------------------------------------------------
// 8) BatchNorm (training-mode batch stats), two deterministic passes
__global__ void __launch_bounds__(256) k_bnred(
    const float* __restrict__ O, const float* __restrict__ gamma,
    const float* __restrict__ beta, float* __restrict__ stat)
{
    int c = blockIdx.x;
    float s = 0.0f, q = 0.0f;
    for (int i = threadIdx.x; i < NPIX; i += 256) {
        int b = i / HWHW, sp = i - b * HWHW;
        float v = O[((size_t)b * CC + c) * HWHW + sp];
        s += v; q += v * v;
    }
    __shared__ float ss[256], qq[256];
    ss[threadIdx.x] = s; qq[threadIdx.x] = q;
    __syncthreads();
    for (int st = 128; st > 0; st >>= 1) {
        if (threadIdx.x < st) {
            ss[threadIdx.x] += ss[threadIdx.x + st];
            qq[threadIdx.x] += qq[threadIdx.x + st];
        }
        __syncthreads();
    }
    if (threadIdx.x == 0) {
        float mean = ss[0] * (1.0f / (float)NPIX);
        float var  = qq[0] * (1.0f / (float)NPIX) - mean * mean;
        float sc = gamma[c] * rsqrtf(var + 1e-5f);
        stat[c] = sc;
        stat[256 + c] = beta[c] - mean * sc;
    }
}

__global__ void k_bnapp(float* __restrict__ O, const float* __restrict__ stat)
{
    int idx = (blockIdx.x * 256 + threadIdx.x) * 2;   // grid covers NF exactly
    float2 v = *(float2*)&O[idx];
    int c = (idx / HWHW) & 255;          // pairs never straddle a channel (HWHW even)
    float scl = stat[c], sh = stat[256 + c];
    v.x = v.x * scl + sh;
    v.y = v.y * scl + sh;
    *(float2*)&O[idx] = v;
}

// ---------------------------------------------------------------------------
extern "C" void kernel_launch(void* const* d_in, const int* in_sizes, int n_in,
                              void* d_out, int out_size)
{
    const float* F_c    = (const float*)d_in[0];
    const float* dec_w  = (const float*)d_in[1];
    const float* dec_b  = (const float*)d_in[2];
    const float* off1_w = (const float*)d_in[3];
    const float* off1_b = (const float*)d_in[4];
    const float* off2_w = (const float*)d_in[5];
    const float* off2_b = (const float*)d_in[6];
    const float* akgdw  = (const float*)d_in[7];
    const float* hw     = (const float*)d_in[8];
    const float* hb     = (const float*)d_in[9];
    const float* pw2_w  = (const float*)d_in[10];
    const float* pw2_b  = (const float*)d_in[11];
    const float* gamma  = (const float*)d_in[12];
    const float* beta   = (const float*)d_in[13];
    float* out = (float*)d_out;

    float* sc = nullptr;
    cudaGetSymbolAddress((void**)&sc, g_scratch);

    float* F0   = sc;
    float* F1   = sc + (size_t)NF;
    float* F0n  = sc + (size_t)2 * NF;
    float* F1n  = sc + (size_t)3 * NF;
    float* D0   = sc + (size_t)4 * NF;
    float* D1   = sc + (size_t)5 * NF;
    float* h    = sc + (size_t)6 * NF;        // 2 * 1605632
    float* pp   = h + 3211264;                 // 2 * 451584
    float* wT1  = pp + 903168;                 // 2 * 147456
    float* wT2  = wT1 + 294912;                // 2 * 36864
    float* wTp  = wT2 + 73728;                 // 131072
    float* dvec = wTp + 131072;                // 4096
    float* Kb   = dvec + 4096;                 // 36864
    float* stat = Kb + 36864;                  // 512

    // 1) decouple
    k_decouple<<<98, 256>>>(F_c, dec_w, dec_b, F0, F1);

    // fused weight transposes
    int wtot = 2 * 2304 * 64 + 2 * 576 * 64 + 512 * 256;
    k_wtrans_all<<<(wtot + 255) / 256, 256>>>(off1_w, off2_w, pw2_w, wT1, wT2, wTp);

    // 2) offset generator convs (both regions per launch)
    dim3 g1(196, 2);
    k_conv3<256, 64, true ><<<g1, 128>>>(F0, F1, wT1, off1_b, h, h + 1605632);
    k_conv3< 64, 18, false><<<g1, 128>>>(h, h + 1605632, wT2, off2_b, pp, pp + 451584);

    // 3) NHWC copies for gather
    k_tr<<<dim3(98, 8, 16), dim3(32, 8)>>>(F0, F1, F0n, F1n);

    // 4/5) AKG
    k_akgpool<<<4096, 64>>>(F0, F1, akgdw, dvec);
    k_akghead<<<dim3(8, 2), 256>>>(dvec, hw, hb, Kb);

    // 6) deformable dynamic depthwise
    k_deform<<<dim3(56, 8, 2), 256>>>(F0n, F1n, pp, pp + 451584, Kb, D0, D1);

    // 7) pointwise merge -> pre-BN output
    k_pw2<<<dim3(196, 4), 128>>>(D0, D1, wTp, pw2_b, out);

    // 8) BN (training-mode batch stats)
    k_bnred<<<256, 256>>>(out, gamma, beta, stat);
    k_bnapp<<<12544, 256>>>(out, stat);
}

// round 4
// speedup vs baseline: 1.6813x; 1.6813x over previous
#include <cuda_runtime.h>
#include <cuda_bf16.h>
#include <math.h>

// Problem constants (fixed shapes)
#define BB 8
#define CC 256
#define HH 56
#define WW 56
#define HWHW 3136            // 56*56
#define NPIX 25088           // B*H*W
#define NF 6422528           // B*C*H*W
#define RR 2
#define HID 64

// ---------------------------------------------------------------------------
// packed f32x2 helpers
__device__ __forceinline__ unsigned long long fma_f32x2(
    unsigned long long a, unsigned long long b, unsigned long long c)
{
    unsigned long long d;
    asm("fma.rn.f32x2 %0, %1, %2, %3;" : "=l"(d) : "l"(a), "l"(b), "l"(c));
    return d;
}
__device__ __forceinline__ unsigned long long pack2(float lo, float hi)
{
    unsigned long long d;
    asm("mov.b64 %0, {%1, %2};" : "=l"(d) : "f"(lo), "f"(hi));
    return d;
}
__device__ __forceinline__ void unpack2(unsigned long long v, float& lo, float& hi)
{
    asm("mov.b64 {%0, %1}, %2;" : "=f"(lo), "=f"(hi) : "l"(v));
}

// ---------------------------------------------------------------------------
// Scratch: single device global (no allocations allowed). ~173 MB.
__device__ __align__(16) float g_scratch[43200000];

// ---------------------------------------------------------------------------
// 1) TargetRegionDecoupler
__global__ void __launch_bounds__(256) k_decouple(
    const float* __restrict__ F, const float* __restrict__ dw,
    const float* __restrict__ db, float* __restrict__ F0, float* __restrict__ F1)
{
    int p = blockIdx.x * 256 + threadIdx.x;
    if (p >= NPIX) return;
    int b = p / HWHW, s = p - b * HWHW;
    const float* base = F + (size_t)b * CC * HWHW + s;
    float l0 = db[0], l1 = db[1];
#pragma unroll 4
    for (int c = 0; c < CC; ++c) {
        float v = base[c * HWHW];
        l0 += v * dw[c];
        l1 += v * dw[CC + c];
    }
    float m0 = 1.0f / (1.0f + expf(l1 - l0));
    float m1 = 1.0f - m0;
    float* o0 = F0 + (size_t)b * CC * HWHW + s;
    float* o1 = F1 + (size_t)b * CC * HWHW + s;
#pragma unroll 4
    for (int c = 0; c < CC; ++c) {
        float v = base[c * HWHW];
        o0[c * HWHW] = v * (1.0f + m0);
        o1[c * HWHW] = v * (1.0f + m1);
    }
}

// ---------------------------------------------------------------------------
// fused weight transposes:  w[OC][K] -> wT[K][OCpad]
__global__ void k_wtrans_all(
    const float* __restrict__ o1w, const float* __restrict__ o2w,
    const float* __restrict__ pww,
    float* __restrict__ wT1, float* __restrict__ wT2, float* __restrict__ wTp)
{
    int idx = blockIdx.x * 256 + threadIdx.x;
    if (idx < 2 * 2304 * 64) {
        int r = idx / (2304 * 64); int e = idx - r * 2304 * 64;
        int k = e / 64, oc = e - k * 64;
        wT1[idx] = (oc < 64) ? o1w[(size_t)r * 64 * 2304 + oc * 2304 + k] : 0.0f;
        return;
    }
    idx -= 2 * 2304 * 64;
    if (idx < 2 * 576 * 64) {
        int r = idx / (576 * 64); int e = idx - r * 576 * 64;
        int k = e / 64, oc = e - k * 64;
        wT2[r * 576 * 64 + e] = (oc < 18) ? o2w[(size_t)r * 18 * 576 + oc * 576 + k] : 0.0f;
        return;
    }
    idx -= 2 * 576 * 64;
    if (idx < 512 * 256) {
        int k = idx / 256, oc = idx - k * 256;
        wTp[idx] = pww[oc * 512 + k];
    }
}

// ---------------------------------------------------------------------------
// 2) 3x3 conv as implicit GEMM, pad=1.  64oc x 128px tile, 128 threads,
//    8x8 microtile. Scalar smem (R1 layout); register-level f32x2 packing.
template<int IC, int OC, bool RELU>
__global__ void __launch_bounds__(128) k_conv3(
    const float* __restrict__ in0, const float* __restrict__ in1,
    const float* __restrict__ wTb, const float* __restrict__ biasb,
    float* __restrict__ out0, float* __restrict__ out1)
{
    const int K = IC * 9;
    int r = blockIdx.y;
    const float* in   = r ? in1 : in0;
    const float* wT   = wTb + (size_t)r * K * 64;
    const float* bias = biasb + r * OC;
    float* out = r ? out1 : out0;

    __shared__ __align__(16) float As[8][64];
    __shared__ __align__(16) float Bs[8][132];
    int tid = threadIdx.x;
    int tr = tid >> 4, tcn = tid & 15;
    int px0 = blockIdx.x * 128;
    int mypx = px0 + tid;
    int mb = mypx / HWHW; int ms = mypx - mb * HWHW;
    int my = ms / WW, mx = ms - my * WW;
    const float* inb = in + (size_t)mb * IC * HWHW;

    unsigned long long acc2[4][8];
#pragma unroll
    for (int i = 0; i < 4; ++i)
#pragma unroll
        for (int j = 0; j < 8; ++j) acc2[i][j] = 0ULL;

    for (int k0 = 0; k0 < K; k0 += 8) {
        // B (im2col on the fly): thread owns one pixel column
#pragma unroll
        for (int j = 0; j < 8; ++j) {
            int k = k0 + j;
            int ic = k / 9, tap = k - ic * 9;
            int ky = tap / 3, kx = tap - ky * 3;
            int yy = my + ky - 1, xx = mx + kx - 1;
            float v = 0.0f;
            if ((unsigned)yy < (unsigned)HH && (unsigned)xx < (unsigned)WW)
                v = __ldg(&inb[ic * HWHW + yy * WW + xx]);
            Bs[j][tid] = v;
        }
        // A: weights already k-major
#pragma unroll
        for (int j = 0; j < 4; ++j) {
            int rrow = (tid >> 6) + j * 2;
            int oc = tid & 63;
            As[rrow][oc] = wT[(k0 + rrow) * 64 + oc];
        }
        __syncthreads();
#pragma unroll
        for (int kk = 0; kk < 8; ++kk) {
            // A pairs: adjacent oc floats form natural (lo,hi) u64 pairs
            ulonglong2 ua0 = *(const ulonglong2*)&As[kk][tr * 8];      // (oc0,oc1),(oc2,oc3)
            ulonglong2 ua1 = *(const ulonglong2*)&As[kk][tr * 8 + 4];  // (oc4,oc5),(oc6,oc7)
            unsigned long long A2[4] = { ua0.x, ua0.y, ua1.x, ua1.y };
            float4 b0 = *(const float4*)&Bs[kk][tcn * 8];
            float4 b1 = *(const float4*)&Bs[kk][tcn * 8 + 4];
            float bv[8] = { b0.x, b0.y, b0.z, b0.w, b1.x, b1.y, b1.z, b1.w };
#pragma unroll
            for (int j = 0; j < 8; ++j) {
                unsigned long long bb = pack2(bv[j], bv[j]);
#pragma unroll
                for (int i2 = 0; i2 < 4; ++i2)
                    acc2[i2][j] = fma_f32x2(A2[i2], bb, acc2[i2][j]);
            }
        }
        __syncthreads();
    }

#pragma unroll
    for (int i2 = 0; i2 < 4; ++i2) {
        int oc0 = tr * 8 + i2 * 2, oc1 = oc0 + 1;
        float bv0 = (oc0 < OC) ? bias[oc0] : 0.0f;
        float bv1 = (oc1 < OC) ? bias[oc1] : 0.0f;
#pragma unroll
        for (int j = 0; j < 8; ++j) {
            float lo, hi; unpack2(acc2[i2][j], lo, hi);
            int px = px0 + tcn * 8 + j;
            int b2 = px / HWHW, s2 = px - b2 * HWHW;
            if (oc0 < OC) {
                float v = lo + bv0; if (RELU) v = fmaxf(v, 0.0f);
                out[((size_t)b2 * OC + oc0) * HWHW + s2] = v;
            }
            if (oc1 < OC) {
                float v = hi + bv1; if (RELU) v = fmaxf(v, 0.0f);
                out[((size_t)b2 * OC + oc1) * HWHW + s2] = v;
            }
        }
    }
}

// ---------------------------------------------------------------------------
// 3) NCHW -> NHWC transpose (per region via blockIdx.z = r*8 + b)
__global__ void k_tr(const float* __restrict__ s0, const float* __restrict__ s1,
                     float* __restrict__ d0, float* __restrict__ d1)
{
    __shared__ float tile[32][33];
    int z = blockIdx.z; int r = z >> 3, b = z & 7;
    const float* src = (r ? s1 : s0) + (size_t)b * CC * HWHW;
    float* dst = (r ? d1 : d0) + (size_t)b * HWHW * CC;
    int c0 = blockIdx.y * 32, sp0 = blockIdx.x * 32;
    int tx = threadIdx.x, ty = threadIdx.y;
#pragma unroll
    for (int i = ty; i < 32; i += 8)
        tile[i][tx] = src[(c0 + i) * HWHW + sp0 + tx];
    __syncthreads();
#pragma unroll
    for (int i = ty; i < 32; i += 8)
        dst[(size_t)(sp0 + i) * CC + c0 + tx] = tile[tx][i];
}

// ---------------------------------------------------------------------------
// 4) AKG part 1
__global__ void __launch_bounds__(64) k_akgpool(
    const float* __restrict__ F0, const float* __restrict__ F1,
    const float* __restrict__ dwwb, float* __restrict__ dvec)
{
    int gb = blockIdx.x; int r = gb >> 11; int bc = gb & 2047;
    int c = bc & 255;
    const float* P = (r ? F1 : F0) + (size_t)bc * HWHW;
    const float* dww = dwwb + r * CC * 9 + c * 9;
    __shared__ float pool[49];
    __shared__ float cnv[49];
    int t = threadIdx.x;
    if (t < 49) {
        int bi = t / 7, bj = t - bi * 7;
        const float* q = P + bi * 8 * WW + bj * 8;
        float sm = 0.0f;
#pragma unroll
        for (int u = 0; u < 8; ++u)
#pragma unroll
            for (int v = 0; v < 8; ++v) sm += q[u * WW + v];
        pool[t] = sm * 0.015625f;
    }
    __syncthreads();
    if (t < 49) {
        int pi = t / 7, pj = t - pi * 7;
        float sm = 0.0f;
#pragma unroll
        for (int u = 0; u < 3; ++u)
#pragma unroll
            for (int v = 0; v < 3; ++v) {
                int yy = pi + u - 1, xx = pj + v - 1;
                if ((unsigned)yy < 7u && (unsigned)xx < 7u)
                    sm += dww[u * 3 + v] * pool[yy * 7 + xx];
            }
        cnv[t] = fmaxf(sm, 0.0f);
    }
    __syncthreads();
    if (t == 0) {
        float sm = 0.0f;
        for (int i = 0; i < 49; ++i) sm += cnv[i];
        dvec[r * 2048 + bc] = sm * (1.0f / 49.0f);
    }
}

// 5) AKG part 2: 1x1 head (2304x256) + tanh
__global__ void __launch_bounds__(256) k_akghead(
    const float* __restrict__ dvec, const float* __restrict__ hwb,
    const float* __restrict__ hbb, float* __restrict__ Kout)
{
    int b = blockIdx.x, r = blockIdx.y;
    const float* hw = hwb + (size_t)r * 2304 * 256;
    const float* hb = hbb + r * 2304;
    __shared__ float dv[256];
    dv[threadIdx.x] = dvec[r * 2048 + b * 256 + threadIdx.x];
    __syncthreads();
    for (int oc = threadIdx.x; oc < 2304; oc += 256) {
        const float* w = hw + (size_t)oc * 256;
        float sm = hb[oc];
#pragma unroll 8
        for (int c2 = 0; c2 < 256; ++c2) sm += w[c2] * dv[c2];
        Kout[(r * 8 + b) * 2304 + oc] = tanhf(sm);
    }
}

// ---------------------------------------------------------------------------
// 6) dynamic depthwise deformable conv (NHWC gather).
__global__ void __launch_bounds__(256) k_deform(
    const float* __restrict__ F0n, const float* __restrict__ F1n,
    const float* __restrict__ p0, const float* __restrict__ p1,
    const float* __restrict__ Kall, float* __restrict__ D0, float* __restrict__ D1)
{
    int y = blockIdx.x, b = blockIdx.y, r = blockIdx.z;
    const float* Fn = (r ? F1n : F0n) + (size_t)b * HWHW * CC;
    const float* off = (r ? p1 : p0) + (size_t)b * 18 * HWHW;
    const float* Kw = Kall + (r * 8 + b) * 2304;
    float* Dn = (r ? D1 : D0) + (size_t)b * HWHW * CC;

    __shared__ int   sIdx[9][56][4];
    __shared__ float sW[9][56][4];
    __shared__ float sK[9][256];
    int tid = threadIdx.x;
    for (int i = tid; i < 2304; i += 256) {
        int c = i / 9, t = i - c * 9;
        sK[t][c] = Kw[i];
    }
    for (int i = tid; i < 504; i += 256) {
        int t = i / 56, x = i - t * 56;
        int ky = t / 3, kx = t - ky * 3;
        float dy = off[(2 * t) * HWHW + y * WW + x];
        float dx = off[(2 * t + 1) * HWHW + y * WW + x];
        float py = (float)(y + ky - 1) + dy;
        float px = (float)(x + kx - 1) + dx;
        float fy = floorf(py), fx = floorf(px);
        float wy1 = py - fy, wx1 = px - fx;
        float wy0 = 1.0f - wy1, wx0 = 1.0f - wx1;
        int y0 = (int)fy, x0 = (int)fx;
        int y1 = y0 + 1, x1 = x0 + 1;
        bool vy0 = (y0 >= 0) && (y0 < HH);
        bool vy1 = (y1 >= 0) && (y1 < HH);
        bool vx0 = (x0 >= 0) && (x0 < WW);
        bool vx1 = (x1 >= 0) && (x1 < WW);
        int cy0 = min(max(y0, 0), HH - 1), cy1 = min(max(y1, 0), HH - 1);
        int cx0 = min(max(x0, 0), WW - 1), cx1 = min(max(x1, 0), WW - 1);
        sIdx[t][x][0] = (cy0 * WW + cx0) * CC; sW[t][x][0] = (vy0 && vx0) ? wy0 * wx0 : 0.0f;
        sIdx[t][x][1] = (cy0 * WW + cx1) * CC; sW[t][x][1] = (vy0 && vx1) ? wy0 * wx1 : 0.0f;
        sIdx[t][x][2] = (cy1 * WW + cx0) * CC; sW[t][x][2] = (vy1 && vx0) ? wy1 * wx0 : 0.0f;
        sIdx[t][x][3] = (cy1 * WW + cx1) * CC; sW[t][x][3] = (vy1 && vx1) ? wy1 * wx1 : 0.0f;
    }
    __syncthreads();
    int lane = tid & 31, wrp = tid >> 5;   // 8 warps; warp owns x stripe
    for (int x = wrp; x < 56; x += 8) {
        float acc[8];
#pragma unroll
        for (int q = 0; q < 8; ++q) acc[q] = 0.0f;
#pragma unroll
        for (int t = 0; t < 9; ++t) {
            int i0 = sIdx[t][x][0], i1 = sIdx[t][x][1];
            int i2 = sIdx[t][x][2], i3 = sIdx[t][x][3];
            float w0 = sW[t][x][0], w1 = sW[t][x][1];
            float w2 = sW[t][x][2], w3 = sW[t][x][3];
#pragma unroll
            for (int q = 0; q < 8; ++q) {
                int c = q * 32 + lane;
                float v = w0 * Fn[i0 + c] + w1 * Fn[i1 + c]
                        + w2 * Fn[i2 + c] + w3 * Fn[i3 + c];
                acc[q] += sK[t][c] * v;
            }
        }
        float* o = Dn + ((size_t)y * WW + x) * CC;
#pragma unroll
        for (int q = 0; q < 8; ++q) o[q * 32 + lane] = acc[q];
    }
}

// ---------------------------------------------------------------------------
// 7) pw2 1x1 conv over concat(D0,D1) (K=512), NHWC input, NCHW output.
//    Scalar smem; register-level f32x2 packing.
__global__ void __launch_bounds__(128) k_pw2(
    const float* __restrict__ D0, const float* __restrict__ D1,
    const float* __restrict__ wT, const float* __restrict__ bias,
    float* __restrict__ out)
{
    __shared__ __align__(16) float As[8][64];
    __shared__ __align__(16) float Bs[8][132];
    int tid = threadIdx.x;
    int tr = tid >> 4, tcn = tid & 15;
    int px0 = blockIdx.x * 128;
    int ocb = blockIdx.y * 64;
    int mypx = px0 + tid;

    unsigned long long acc2[4][8];
#pragma unroll
    for (int i = 0; i < 4; ++i)
#pragma unroll
        for (int j = 0; j < 8; ++j) acc2[i][j] = 0ULL;

    for (int k0 = 0; k0 < 512; k0 += 8) {
        const float* src = (k0 < 256) ? (D0 + (size_t)mypx * 256 + k0)
                                      : (D1 + (size_t)mypx * 256 + (k0 - 256));
        float4 v0 = *(const float4*)src;
        float4 v1 = *(const float4*)(src + 4);
        Bs[0][tid] = v0.x; Bs[1][tid] = v0.y; Bs[2][tid] = v0.z; Bs[3][tid] = v0.w;
        Bs[4][tid] = v1.x; Bs[5][tid] = v1.y; Bs[6][tid] = v1.z; Bs[7][tid] = v1.w;
#pragma unroll
        for (int j = 0; j < 4; ++j) {
            int rrow = (tid >> 6) + j * 2;
            int oc = tid & 63;
            As[rrow][oc] = wT[(k0 + rrow) * 256 + ocb + oc];
        }
        __syncthreads();
#pragma unroll
        for (int kk = 0; kk < 8; ++kk) {
            ulonglong2 ua0 = *(const ulonglong2*)&As[kk][tr * 8];
            ulonglong2 ua1 = *(const ulonglong2*)&As[kk][tr * 8 + 4];
            unsigned long long A2[4] = { ua0.x, ua0.y, ua1.x, ua1.y };
            float4 b0 = *(const float4*)&Bs[kk][tcn * 8];
            float4 b1 = *(const float4*)&Bs[kk][tcn * 8 + 4];
            float bv[8] = { b0.x, b0.y, b0.z, b0.w, b1.x, b1.y, b1.z, b1.w };
#pragma unroll
            for (int j = 0; j < 8; ++j) {
                unsigned long long bb = pack2(bv[j], bv[j]);
#pragma unroll
                for (int i2 = 0; i2 < 4; ++i2)
                    acc2[i2][j] = fma_f32x2(A2[i2], bb, acc2[i2][j]);
            }
        }
        __syncthreads();
    }

#pragma unroll
    for (int i2 = 0; i2 < 4; ++i2) {
        int oc0 = ocb + tr * 8 + i2 * 2, oc1 = oc0 + 1;
        float bv0 = bias[oc0], bv1 = bias[oc1];
#pragma unroll
        for (int j = 0; j < 8; ++j) {
            float lo, hi; unpack2(acc2[i2][j], lo, hi);
            int px = px0 + tcn * 8 + j;
            int b2 = px / HWHW, s2 = px - b2 * HWHW;
            out[((size_t)b2 * CC + oc0) * HWHW + s2] = lo + bv0;
            out[((size_t)b2 * CC + oc1) * HWHW + s2] = hi + bv1;
        }
    }
}

// ---------------------------------------------------------------------------
// 8) BatchNorm (training-mode batch stats), two deterministic passes
__global__ void __launch_bounds__(256) k_bnred(
    const float* __restrict__ O, const float* __restrict__ gamma,
    const float* __restrict__ beta, float* __restrict__ stat)
{
    int c = blockIdx.x;
    float s = 0.0f, q = 0.0f;
    for (int i = threadIdx.x; i < NPIX; i += 256) {
        int b = i / HWHW, sp = i - b * HWHW;
        float v = O[((size_t)b * CC + c) * HWHW + sp];
        s += v; q += v * v;
    }
    __shared__ float ss[256], qq[256];
    ss[threadIdx.x] = s; qq[threadIdx.x] = q;
    __syncthreads();
    for (int st = 128; st > 0; st >>= 1) {
        if (threadIdx.x < st) {
            ss[threadIdx.x] += ss[threadIdx.x + st];
            qq[threadIdx.x] += qq[threadIdx.x + st];
        }
        __syncthreads();
    }
    if (threadIdx.x == 0) {
        float mean = ss[0] * (1.0f / (float)NPIX);
        float var  = qq[0] * (1.0f / (float)NPIX) - mean * mean;
        float sc = gamma[c] * rsqrtf(var + 1e-5f);
        stat[c] = sc;
        stat[256 + c] = beta[c] - mean * sc;
    }
}

__global__ void k_bnapp(float* __restrict__ O, const float* __restrict__ stat)
{
    int idx = (blockIdx.x * 256 + threadIdx.x) * 2;   // grid covers NF exactly
    float2 v = *(float2*)&O[idx];
    int c = (idx / HWHW) & 255;
    float scl = stat[c], sh = stat[256 + c];
    v.x = v.x * scl + sh;
    v.y = v.y * scl + sh;
    *(float2*)&O[idx] = v;
}

// ---------------------------------------------------------------------------
extern "C" void kernel_launch(void* const* d_in, const int* in_sizes, int n_in,
                              void* d_out, int out_size)
{
    const float* F_c    = (const float*)d_in[0];
    const float* dec_w  = (const float*)d_in[1];
    const float* dec_b  = (const float*)d_in[2];
    const float* off1_w = (const float*)d_in[3];
    const float* off1_b = (const float*)d_in[4];
    const float* off2_w = (const float*)d_in[5];
    const float* off2_b = (const float*)d_in[6];
    const float* akgdw  = (const float*)d_in[7];
    const float* hw     = (const float*)d_in[8];
    const float* hb     = (const float*)d_in[9];
    const float* pw2_w  = (const float*)d_in[10];
    const float* pw2_b  = (const float*)d_in[11];
    const float* gamma  = (const float*)d_in[12];
    const float* beta   = (const float*)d_in[13];
    float* out = (float*)d_out;

    float* sc = nullptr;
    cudaGetSymbolAddress((void**)&sc, g_scratch);

    float* F0   = sc;
    float* F1   = sc + (size_t)NF;
    float* F0n  = sc + (size_t)2 * NF;
    float* F1n  = sc + (size_t)3 * NF;
    float* D0   = sc + (size_t)4 * NF;
    float* D1   = sc + (size_t)5 * NF;
    float* h    = sc + (size_t)6 * NF;        // 2 * 1605632
    float* pp   = h + 3211264;                 // 2 * 451584
    float* wT1  = pp + 903168;                 // 2 * 147456
    float* wT2  = wT1 + 294912;                // 2 * 36864
    float* wTp  = wT2 + 73728;                 // 131072
    float* dvec = wTp + 131072;                // 4096
    float* Kb   = dvec + 4096;                 // 36864
    float* stat = Kb + 36864;                  // 512

    // 1) decouple
    k_decouple<<<98, 256>>>(F_c, dec_w, dec_b, F0, F1);

    // fused weight transposes
    int wtot = 2 * 2304 * 64 + 2 * 576 * 64 + 512 * 256;
    k_wtrans_all<<<(wtot + 255) / 256, 256>>>(off1_w, off2_w, pw2_w, wT1, wT2, wTp);

    // 2) offset generator convs (both regions per launch)
    dim3 g1(196, 2);
    k_conv3<256, 64, true ><<<g1, 128>>>(F0, F1, wT1, off1_b, h, h + 1605632);
    k_conv3< 64, 18, false><<<g1, 128>>>(h, h + 1605632, wT2, off2_b, pp, pp + 451584);

    // 3) NHWC copies for gather
    k_tr<<<dim3(98, 8, 16), dim3(32, 8)>>>(F0, F1, F0n, F1n);

    // 4/5) AKG
    k_akgpool<<<4096, 64>>>(F0, F1, akgdw, dvec);
    k_akghead<<<dim3(8, 2), 256>>>(dvec, hw, hb, Kb);

    // 6) deformable dynamic depthwise
    k_deform<<<dim3(56, 8, 2), 256>>>(F0n, F1n, pp, pp + 451584, Kb, D0, D1);

    // 7) pointwise merge -> pre-BN output
    k_pw2<<<dim3(196, 4), 128>>>(D0, D1, wTp, pw2_b, out);

    // 8) BN (training-mode batch stats)
    k_bnred<<<256, 256>>>(out, gamma, beta, stat);
    k_bnapp<<<12544, 256>>>(out, stat);
}